// round 17
// baseline (speedup 1.0000x reference)
#include <cuda_runtime.h>
#include <cuda_bf16.h>
#include <math.h>
#include <stdint.h>

#define Bn 16
#define Qn 4096
#define Gn 256
#define Cn 80
#define Ks 16   // shortlist size per column
#define NBLK 8  // q-chunks per column in cost kernel (512 q each)

// ---------------- device scratch ----------------
__device__ float g_tab[(size_t)Bn * Cn * Qn];          // [b][c][q]
__device__ unsigned char g_fgm[(size_t)Bn * Qn];
__device__ float g_cost[(size_t)Bn * Gn * Qn];         // [b][g][q]
__device__ float g_i5[(size_t)Bn * Gn * NBLK * 5];     // per-chunk iou top5 partials
__device__ int g_dk[(size_t)Bn * Gn];
__device__ int g_sidx[(size_t)Bn * Gn * Ks];           // lexicographic (cost,q) top-16 per column

// ---------------- helpers ----------------
__device__ __forceinline__ void warpMinPair(float &v, int &i) {
#pragma unroll
    for (int off = 16; off; off >>= 1) {
        float ov = __shfl_xor_sync(0xffffffffu, v, off);
        int   oi = __shfl_xor_sync(0xffffffffu, i, off);
        if (ov < v || (ov == v && oi < i)) { v = ov; i = oi; }
    }
}

// FMA-pipe natural log (Cephes-style, ~1ulp), no MUFU usage.
__device__ __forceinline__ float fma_log(float v) {
    unsigned ix = __float_as_uint(v);
    unsigned ex = (ix - 0x3f3504f3u) & 0xff800000u;
    float m = __uint_as_float(ix - ex);
    float k = (float)((int)ex >> 23);
    float f = m - 1.0f;
    float z = f * f;
    float p = 7.0376836292e-2f;
    p = fmaf(p, f, -1.1514610310e-1f);
    p = fmaf(p, f,  1.1676998740e-1f);
    p = fmaf(p, f, -1.2420140846e-1f);
    p = fmaf(p, f,  1.4249322787e-1f);
    p = fmaf(p, f, -1.6668057665e-1f);
    p = fmaf(p, f,  2.0000714765e-1f);
    p = fmaf(p, f, -2.4999993993e-1f);
    p = fmaf(p, f,  3.3333331174e-1f);
    float y = p * f * z;
    y = fmaf(-2.12194440e-4f, k, y);
    y = fmaf(-0.5f, z, y);
    float r = f + y;
    return fmaf(0.693359375f, k, r);
}

// ---------------- K0: class cost table ----------------
__global__ void tab_kernel(const float* __restrict__ logits) {
    int idx = blockIdx.x * 256 + threadIdx.x;
    if (idx >= Bn * Qn) return;
    const float4* row = reinterpret_cast<const float4*>(logits + (size_t)idx * Cn);
    float* dst = g_tab + ((size_t)(idx / Qn) * Cn) * Qn + (idx % Qn);
#pragma unroll 4
    for (int c4 = 0; c4 < Cn / 4; c4++) {
        float4 xv = row[c4];
        float xs[4] = {xv.x, xv.y, xv.z, xv.w};
#pragma unroll
        for (int j = 0; j < 4; j++) {
            float x = xs[j];
            float e = __expf(-x);
            float pr = __fdividef(1.0f, 1.0f + e);
            float om = 1.0f - pr;
            float neg = 0.75f * (pr * pr) * (-fma_log(om + 1e-8f));
            float pos = 0.25f * (om * om) * (-fma_log(pr + 1e-8f));
            dst[(size_t)(c4 * 4 + j) * Qn] = pos - neg;
        }
    }
}

// ---------------- K1: fg mask ----------------
__global__ void fg_kernel(const float* __restrict__ pred_boxes,
                          const float* __restrict__ gt_boxes) {
    __shared__ float s[Gn][8];
    int b = blockIdx.y;
    int q = blockIdx.x * 256 + threadIdx.x;
    int tid = threadIdx.x;
    {
        const float* gb = gt_boxes + ((size_t)b * Gn + tid) * 4;
        float gx0 = gb[0], gy0 = gb[1], gx1 = gb[2], gy1 = gb[3];
        float cx = (gx0 + gx1) * 0.5f, cy = (gy0 + gy1) * 0.5f;
        float gw = gx1 - gx0, gh = gy1 - gy0;
        float x0 = cx - gw * 0.5f, y0 = cy - gh * 0.5f;
        float x1 = cx + gw * 0.5f, y1 = cy + gh * 0.5f;
        float w = x1 - x0, h = y1 - y0;
        s[tid][0] = x0; s[tid][1] = y0; s[tid][2] = x1; s[tid][3] = y1;
        s[tid][4] = cx - 2.5f * w; s[tid][5] = cx + 2.5f * w;
        s[tid][6] = cy - 2.5f * h; s[tid][7] = cy + 2.5f * h;
    }
    __syncthreads();
    float4 p = reinterpret_cast<const float4*>(pred_boxes)[(size_t)b * Qn + q];
    float ax = (p.x + p.z) * 0.5f, ay = (p.y + p.w) * 0.5f;
    unsigned char fg = 0;
    for (int g = 0; g < Gn; g++) {
        bool ib = (ax > s[g][0]) && (ax < s[g][2]) && (ay > s[g][1]) && (ay < s[g][3]);
        bool ic = (ax > s[g][4]) && (ax < s[g][5]) && (ay > s[g][6]) && (ay < s[g][7]);
        if (ib || ic) { fg = 1; break; }
    }
    g_fgm[(size_t)b * Qn + q] = fg;
}

// ---------------- K2: cost, warp-per-column (registers, no smem, no barriers) ----------------
__global__ void cost_kernel(const float* __restrict__ pred_boxes,
                            const float* __restrict__ pred_poses,
                            const int*   __restrict__ labels,
                            const float* __restrict__ gt_boxes,
                            const float* __restrict__ gt_t,
                            const float* __restrict__ gt_r,
                            const float* __restrict__ isz,
                            const float* __restrict__ iszt) {
    int wrp = threadIdx.x >> 5, lane = threadIdx.x & 31;
    int b  = blockIdx.z;
    int g  = blockIdx.y * 8 + wrp;
    int q0 = blockIdx.x * 512;

    // per-warp gt constants (broadcast LDG, amortized over 512 q)
    const float* gb = gt_boxes + ((size_t)b * Gn + g) * 4;
    float gx0 = gb[0], gy0 = gb[1], gx1 = gb[2], gy1 = gb[3];
    const float* t3 = gt_t + ((size_t)b * Gn + g) * 3;
    float t0 = t3[0], t1 = t3[1], t2 = t3[2];
    const float* r3 = gt_r + ((size_t)b * Gn + g) * 3;
    float r0 = r3[0], r1 = r3[1], r2 = r3[2];
    const float* ist = iszt + ((size_t)b * Gn + g) * 4;
    float gn0 = gx0 / ist[0], gn1 = gy0 / ist[1], gn2 = gx1 / ist[2], gn3 = gy1 / ist[3];
    int lab = labels[b * Gn + g];
    const float* is = isz + (size_t)b * 4;
    float is0 = is[0], is1 = is[1], is2 = is[2], is3 = is[3];

    float area2 = (gx1 - gx0) * (gy1 - gy0);
    float gcx = (gx0 + gx1) * 0.5f, gcy = (gy0 + gy1) * 0.5f;
    float gw = gx1 - gx0, gh = gy1 - gy0;
    float bx0 = gcx - gw * 0.5f, by0 = gcy - gh * 0.5f;
    float bx1 = gcx + gw * 0.5f, by1 = gcy + gh * 0.5f;
    float w = bx1 - bx0, h = by1 - by0;
    float ctx0 = gcx - 2.5f * w, ctx1 = gcx + 2.5f * w;
    float cty0 = gcy - 2.5f * h, cty1 = gcy + 2.5f * h;

    const float4* pb4 = reinterpret_cast<const float4*>(pred_boxes) + (size_t)b * Qn;
    const float2* pp2 = reinterpret_cast<const float2*>(pred_poses) + (size_t)b * Qn * 3;
    const float* tabp = g_tab + ((size_t)b * Cn + lab) * Qn;
    const unsigned char* fgp = g_fgm + (size_t)b * Qn;
    float* dstc = g_cost + ((size_t)b * Gn + g) * Qn;

    float iv[5];
#pragma unroll
    for (int k = 0; k < 5; k++) iv[k] = -INFINITY;

#pragma unroll 4
    for (int i = 0; i < 16; i++) {
        int q = q0 + lane + 32 * i;
        float4 p = pb4[q];
        float2 pa = pp2[q * 3], pbp = pp2[q * 3 + 1], pc = pp2[q * 3 + 2];

        float area1 = (p.z - p.x) * (p.w - p.y);
        float lx = fmaxf(p.x, gx0), ly = fmaxf(p.y, gy0);
        float rx = fminf(p.z, gx1), ry = fminf(p.w, gy1);
        float wx = fmaxf(rx - lx, 0.0f), wy = fmaxf(ry - ly, 0.0f);
        float inter = wx * wy;
        float uni = area1 + area2 - inter;
        float iou = inter / uni;
        float Lx = fminf(p.x, gx0), Ly = fminf(p.y, gy0);
        float Rx = fmaxf(p.z, gx1), Ry = fmaxf(p.w, gy1);
        float ew = fmaxf(Rx - Lx, 0.0f), eh = fmaxf(Ry - Ly, 0.0f);
        float areaE = ew * eh;
        float giou = iou - (areaE - uni) / areaE;

        float nx0 = p.x / is0, ny0 = p.y / is1, nx1 = p.z / is2, ny1 = p.w / is3;
        float cb = fabsf(nx0 - gn0) + fabsf(ny0 - gn1) + fabsf(nx1 - gn2) + fabsf(ny1 - gn3);

        float cc = tabp[q];

        float ct = fabsf(pa.x - t0) + fabsf(pa.y - t1) + fabsf(pbp.x - t2);
        float cr = fabsf(pbp.y - r0) + fabsf(pc.x - r1) + fabsf(pc.y - r2);

        float ax = (p.x + p.z) * 0.5f, ay = (p.y + p.w) * 0.5f;
        bool in_box = (ax > bx0) && (ax < bx1) && (ay > by0) && (ay < by1);
        bool in_ctr = (ax > ctx0) && (ax < ctx1) && (ay > cty0) && (ay < cty1);
        bool both = in_box && in_ctr;

        float cost = 5.0f * cb + 2.0f * cc + 2.0f * (-giou)
                   + 100.0f * (both ? 0.0f : 1.0f) + 1.0f * ct + 1.0f * cr
                   + (fgp[q] ? 0.0f : 10000.0f);

        dstc[q] = cost;

        if (iou > iv[4]) {
            iv[4] = iou;
#pragma unroll
            for (int k = 4; k > 0; k--) {
                float lo = fminf(iv[k], iv[k - 1]);
                float hi = fmaxf(iv[k], iv[k - 1]);
                iv[k] = lo; iv[k - 1] = hi;
            }
        }
    }

    // one 5-round warp extraction per (g, chunk)
    int pr = 0;
    float* dst = g_i5 + (((size_t)b * Gn + g) * NBLK + blockIdx.x) * 5;
    for (int r = 0; r < 5; r++) {
        float c = (pr < 5) ? iv[pr] : -INFINITY;
        float m = c;
#pragma unroll
        for (int off = 16; off; off >>= 1) m = fmaxf(m, __shfl_xor_sync(0xffffffffu, m, off));
        unsigned ball = __ballot_sync(0xffffffffu, c == m);
        if (lane == (__ffs(ball) - 1)) pr++;
        if (lane == 0) dst[r] = m;
    }
}

// ---------------- K3: dk from partials (warp per column, 40 values) ----------------
__global__ void dk_kernel() {
    int wrp = threadIdx.x >> 5, lane = threadIdx.x & 31;
    int g = blockIdx.x * 8 + wrp;
    int b = blockIdx.y;
    const float* src = g_i5 + ((size_t)b * Gn + g) * NBLK * 5;   // 40 floats

    float a0 = src[lane];
    float a1 = (lane < 8) ? src[lane + 32] : -INFINITY;
    if (a1 > a0) { float t = a0; a0 = a1; a1 = t; }

    int pr = 0; float sum = 0.0f;
    for (int r = 0; r < 5; r++) {
        float c = (pr == 0) ? a0 : (pr == 1) ? a1 : -INFINITY;
        float m = c;
#pragma unroll
        for (int off = 16; off; off >>= 1) m = fmaxf(m, __shfl_xor_sync(0xffffffffu, m, off));
        sum += m;
        unsigned ball = __ballot_sync(0xffffffffu, c == m);
        if (lane == (__ffs(ball) - 1)) pr++;
    }
    int dk = (int)sum;
    if (dk < 1) dk = 1;
    if (dk > 5) dk = 5;
    if (lane == 0) g_dk[(size_t)b * Gn + g] = dk;
}

// ---------------- K4: per-column lexicographic cost top-16 (u64 keys) ----------------
__device__ __forceinline__ unsigned long long costKey(float v, int q) {
    unsigned bits = __float_as_uint(v);
    unsigned mk = (bits & 0x80000000u) ? ~bits : (bits ^ 0x80000000u);
    return ((unsigned long long)mk << 32) | (unsigned)q;
}

__global__ void short_kernel() {
    int warp = threadIdx.x >> 5, lane = threadIdx.x & 31;
    int col = blockIdx.x * 4 + warp;
    const float4* c4 = reinterpret_cast<const float4*>(g_cost + (size_t)col * Qn);

    unsigned long long t[Ks];
#pragma unroll
    for (int k = 0; k < Ks; k++) t[k] = ~0ull;

    for (int i = lane; i < Qn / 4; i += 32) {
        float4 v = c4[i];
        int q0 = i * 4;
#pragma unroll
        for (int j = 0; j < 4; j++) {
            float vv = (j == 0) ? v.x : (j == 1) ? v.y : (j == 2) ? v.z : v.w;
            unsigned long long key = costKey(vv, q0 + j);
            if (key < t[Ks - 1]) {
                t[Ks - 1] = key;
#pragma unroll
                for (int k = Ks - 1; k > 0; k--) {
                    unsigned long long a = t[k - 1], bb = t[k];
                    t[k - 1] = (a < bb) ? a : bb;
                    t[k]     = (a < bb) ? bb : a;
                }
            }
        }
    }

    int p = 0;
    int* dst = g_sidx + (size_t)col * Ks;
    for (int r = 0; r < Ks; r++) {
        unsigned long long cand = (p < Ks) ? t[p] : ~0ull;
        unsigned long long m = cand;
#pragma unroll
        for (int off = 16; off; off >>= 1) {
            unsigned long long o = __shfl_xor_sync(0xffffffffu, m, off);
            if (o < m) m = o;
        }
        if (cand == m) {
            p++;
            dst[r] = (int)(m & 0xffffffffu);
        }
    }
}

// ---------------- K5: matching (all shared, no bitmask) ----------------
__global__ void __launch_bounds__(1024, 1) match_kernel(float* __restrict__ out) {
    int b = blockIdx.x, tid = threadIdx.x;
    int wid = tid >> 5, lane = tid & 31;
    const float* Cb = g_cost + (size_t)b * Gn * Qn;
    const int* sidx = g_sidx + (size_t)b * Gn * Ks;

    __shared__ int s_rcnt[Qn];
    __shared__ unsigned char s_pen[Qn];
    __shared__ int s_ming[Qn];
    __shared__ unsigned char s_rg8[Qn];
    __shared__ unsigned s_mat[Qn / 32];
    __shared__ unsigned s_stale[Qn / 32];
    __shared__ int s_col[Gn];
    __shared__ unsigned char s_dk[Gn];
    __shared__ short s_asg[Gn];
    __shared__ unsigned short s_un[Gn], s_fb[Gn];
    __shared__ unsigned short s_slist[1024];
    __shared__ int s_ucnt, s_fbcnt, s_scnt;

    for (int i = tid; i < Qn; i += 1024) { s_rcnt[i] = 0; s_pen[i] = 0; s_ming[i] = 0x7fffffff; }
    for (int i = tid; i < Qn / 32; i += 1024) s_stale[i] = 0u;
    if (tid < Gn) { s_dk[tid] = (unsigned char)g_dk[b * Gn + tid]; s_col[tid] = 0; s_asg[tid] = -1; }
    if (tid == 0) s_scnt = 0;
    __syncthreads();

    if (tid < Gn) {
        int dk = s_dk[tid];
        for (int j = 0; j < dk; j++) atomicAdd(&s_rcnt[sidx[tid * Ks + j]], 1);
    }
    __syncthreads();
    for (int q = tid; q < Qn; q += 1024)
        if (s_rcnt[q] > 1) {
            atomicOr(&s_stale[q >> 5], 1u << (q & 31));
            int k = atomicAdd(&s_scnt, 1);
            if (k < 1024) s_slist[k] = (unsigned short)q;
        }
    __syncthreads();
    int ns = s_scnt; if (ns > 1024) ns = 1024;
    for (int s = wid; s < ns; s += 32) {
        int q = s_slist[s];
        float bv = INFINITY; int bg = 0;
        for (int g = lane; g < Gn; g += 32) {
            float v = Cb[(size_t)g * Qn + q];
            if (v < bv) { bv = v; bg = g; }
        }
        warpMinPair(bv, bg);
        if (lane == 0) s_rg8[q] = (unsigned char)bg;
    }
    __syncthreads();
    for (int q = tid; q < Qn; q += 1024) s_rcnt[q] = 0;
    __syncthreads();
    if (tid < Gn) {
        int dk = s_dk[tid];
        for (int j = 0; j < dk; j++) {
            int q = sidx[tid * Ks + j];
            if (!((s_stale[q >> 5] >> (q & 31)) & 1)) {
                atomicAdd(&s_rcnt[q], 1);
                atomicAdd(&s_col[tid], 1);
                atomicMin(&s_ming[q], tid);
            }
        }
    }
    for (int s = tid; s < ns; s += 1024) {
        int q = s_slist[s];
        int rg = s_rg8[q];
        s_rcnt[q] = 1;
        s_ming[q] = rg;
        atomicAdd(&s_col[rg], 1);
    }
    __syncthreads();

    for (int it = 0; it < Gn; it++) {
        if (tid == 0) { s_ucnt = 0; s_fbcnt = 0; }
        __syncthreads();
        if (tid < Gn && s_col[tid] == 0) {
            int k = atomicAdd(&s_ucnt, 1); s_un[k] = (unsigned short)tid;
        }
        __syncthreads();
        int nu = s_ucnt;
        if (nu == 0) break;
        for (int q = tid; q < Qn; q += 1024) if (s_rcnt[q] > 0) s_pen[q]++;
        if (tid < Qn / 32) {
            unsigned wb = 0;
#pragma unroll 8
            for (int j = 0; j < 32; j++) if (s_rcnt[tid * 32 + j] > 0) wb |= 1u << j;
            s_mat[tid] = wb;
        }
        __syncthreads();
        if (tid < nu) {
            int g = s_un[tid];
            int chosen = -1;
            for (int j = 0; j < Ks; j++) {
                int q = sidx[g * Ks + j];
                if (!((s_mat[q >> 5] >> (q & 31)) & 1)) { chosen = q; break; }
            }
            if (chosen >= 0) {
                atomicAdd(&s_rcnt[chosen], 1);
                atomicMin(&s_ming[chosen], g);
                s_col[g] = 1;
                s_asg[g] = (short)chosen;
            } else {
                int k = atomicAdd(&s_fbcnt, 1); s_fb[k] = (unsigned short)g;
            }
        }
        __syncthreads();
        int nfb = s_fbcnt;
        for (int u = wid; u < nfb; u += 32) {
            int g = s_fb[u];
            const float* col = Cb + (size_t)g * Qn;
            float bv = INFINITY; int bi = 0;
            for (int q = lane; q < Qn; q += 32) {
                if (!((s_mat[q >> 5] >> (q & 31)) & 1)) {
                    float v = col[q];
                    if (v < bv) { bv = v; bi = q; }
                }
            }
            warpMinPair(bv, bi);
            if (bv == INFINITY) {
                bv = INFINITY; bi = 0;
                for (int q = lane; q < Qn; q += 32) {
                    float v = col[q] + 100000.0f * (float)s_pen[q];
                    if (v < bv) { bv = v; bi = q; }
                }
                warpMinPair(bv, bi);
            }
            if (lane == 0) {
                atomicAdd(&s_rcnt[bi], 1);
                atomicMin(&s_ming[bi], g);
                s_col[g] = 1;
                s_asg[g] = (short)bi;
            }
        }
        __syncthreads();
    }

    float* out_sel = out;
    float* out_gt  = out + Bn * Qn;
    float* out_mq  = out + 2 * Bn * Qn;
    for (int q = tid; q < Qn; q += 1024) {
        int r = s_rcnt[q];
        out_sel[(size_t)b * Qn + q] = (r > 0) ? 1.0f : 0.0f;
        out_gt[(size_t)b * Qn + q] = (r > 0) ? (float)s_ming[q] : 0.0f;
    }
    if (tid < Gn) {
        int g = tid;
        const float* col = Cb + (size_t)g * Qn;
        float bv = INFINITY; int bi = 0;
        int dk = s_dk[g];
        for (int j = 0; j < dk; j++) {
            int q = sidx[g * Ks + j];
            if (!((s_stale[q >> 5] >> (q & 31)) & 1)) {
                float v = col[q];
                int p = s_pen[q];
                for (int k = 0; k < p; k++) v += 100000.0f;
                if (v < bv || (v == bv && q < bi)) { bv = v; bi = q; }
            }
        }
        for (int s = 0; s < ns; s++) {
            int q = s_slist[s];
            if (s_rg8[q] == g) {
                float v = col[q];
                int p = s_pen[q];
                for (int k = 0; k < p; k++) v += 100000.0f;
                if (v < bv || (v == bv && q < bi)) { bv = v; bi = q; }
            }
        }
        int aq = s_asg[g];
        if (aq >= 0) {
            float v = col[aq];
            int p = s_pen[aq];
            for (int k = 0; k < p; k++) v += 100000.0f;
            if (v < bv || (v == bv && aq < bi)) { bv = v; bi = aq; }
        }
        out_mq[(size_t)b * Gn + g] = (float)bi;
    }
}

// ---------------- launch ----------------
extern "C" void kernel_launch(void* const* d_in, const int* in_sizes, int n_in,
                              void* d_out, int out_size) {
    const float* pred_logits = (const float*)d_in[0];
    const float* pred_boxes  = (const float*)d_in[1];
    const float* pred_poses  = (const float*)d_in[2];
    const int*   labels      = (const int*)  d_in[3];
    const float* gt_boxes    = (const float*)d_in[4];
    const float* gt_trans    = (const float*)d_in[5];
    const float* gt_rot      = (const float*)d_in[6];
    const float* isz         = (const float*)d_in[7];
    const float* iszt        = (const float*)d_in[8];
    float* out = (float*)d_out;

    tab_kernel<<<(Bn * Qn + 255) / 256, 256>>>(pred_logits);
    fg_kernel<<<dim3(Qn / 256, Bn), 256>>>(pred_boxes, gt_boxes);
    cost_kernel<<<dim3(NBLK, Gn / 8, Bn), 256>>>(pred_boxes, pred_poses, labels,
                                                 gt_boxes, gt_trans, gt_rot, isz, iszt);
    short_kernel<<<(Bn * Gn) / 4, 128>>>();   // slot 4: profiled next round
    dk_kernel<<<dim3(Gn / 8, Bn), 256>>>();
    match_kernel<<<Bn, 1024>>>(out);
}